// round 5
// baseline (speedup 1.0000x reference)
#include <cuda_runtime.h>
#include <cstdint>

// Problem constants (fixed by reference)
#define NN    16384   // n_nodes
#define D_IN  128
#define D_H   64
#define BB    4096    // minibatch

// Device scratch (no allocations allowed)
__device__ float g_enc[NN * D_H];           // 4 MiB: encoder output
__device__ float g_rowout2[2][NN * D_H];    // 8 MiB: per-half-row partials
__device__ int   g_idx[BB];
__device__ int   g_rows[BB];                // unique row worklist
__device__ int   g_flag[NN];
__device__ int   g_nuniq;
__device__ int   g_work;

// ---------------------------------------------------------------------------
// K1 prep: zero flags/counters + decode idx (int64 vs int32).
// Detection window is IDENTICAL and IN-BOUNDS for every decode block: odd
// int32 words of entries 0..255 (word idx 1..511 — safe for either layout).
// ---------------------------------------------------------------------------
__global__ void __launch_bounds__(256) prep_kernel(const int* __restrict__ idx32) {
    const int b = blockIdx.x, tid = threadIdx.x;
    if (b < 16) {
#pragma unroll
        for (int u = 0; u < 4; u++) g_flag[b * 1024 + u * 256 + tid] = 0;
        if (b == 0 && tid == 0) { g_nuniq = 0; g_work = 0; }
    } else {
        __shared__ int s_is64;
        if (tid == 0) s_is64 = 1;
        __syncthreads();
        if (idx32[2 * tid + 1] != 0) s_is64 = 0;   // safe window; benign race
        __syncthreads();
        const int i = (b - 16) * 256 + tid;
        g_idx[i] = s_is64 ? idx32[2 * i] : idx32[i];
    }
}

// ---------------------------------------------------------------------------
// K2: enc = X @ W + b -> g_enc [NN,64]; 4 extra blocks build the unique-row
// worklist from g_idx.
// ---------------------------------------------------------------------------
__global__ void __launch_bounds__(256) enc_kernel(const float* __restrict__ X,
                                                  const float* __restrict__ W,
                                                  const float* __restrict__ b) {
    if (blockIdx.x >= NN / 32) {
        const int base = (blockIdx.x - NN / 32) * 1024 + threadIdx.x;
#pragma unroll
        for (int u = 0; u < 4; u++) {
            const int row = g_idx[base + u * 256];
            if (atomicExch(&g_flag[row], 1) == 0) {
                const int p = atomicAdd(&g_nuniq, 1);
                g_rows[p] = row;
            }
        }
        return;
    }

    __shared__ float sW[D_IN * D_H];   // 32 KiB
    __shared__ float sX[32 * D_IN];    // 16 KiB
    const int tid = threadIdx.x;

    for (int i = tid; i < D_IN * D_H; i += 256) sW[i] = W[i];
    const int row0 = blockIdx.x * 32;
    for (int i = tid; i < 32 * D_IN; i += 256) sX[i] = X[(size_t)row0 * D_IN + i];
    __syncthreads();

    const int c  = tid & 63;
    const int r0 = tid >> 6;
    const float bc = b[c];
    float acc[8];
#pragma unroll
    for (int a = 0; a < 8; a++) acc[a] = bc;

#pragma unroll 4
    for (int k = 0; k < D_IN; k++) {
        const float w = sW[k * D_H + c];
#pragma unroll
        for (int a = 0; a < 8; a++)
            acc[a] += sX[(r0 + 4 * a) * D_IN + k] * w;
    }
#pragma unroll
    for (int a = 0; a < 8; a++)
        g_enc[(size_t)(row0 + r0 + 4 * a) * D_H + c] = acc[a];
}

// ---------------------------------------------------------------------------
// K3: persistent gather over HALF-ROW chunks (fine-grain queue -> no tail
// quantization). Each chunk: 4 warps x 8KB; per warp 16 uint4 in flight
// (one burst, MLP=16), integer-OR zero test, nonzeros to per-warp smem list,
// replay vs L2-resident g_enc, block reduce, write partial to g_rowout2.
// No atomics in the accumulation -> deterministic; no zero-init needed
// (both halves of every unique row are written each launch).
// ---------------------------------------------------------------------------
__global__ void __launch_bounds__(128) gather_kernel(const float* __restrict__ ppr) {
    __shared__ float vbuf[4][144];
    __shared__ int   jbuf[4][144];
    __shared__ int   cnt[4];
    __shared__ float red[4][D_H];
    __shared__ int   s_cid;

    const int lane = threadIdx.x & 31;
    const int warp = threadIdx.x >> 5;
    const int nchunks = 2 * g_nuniq;

    for (;;) {
        if (threadIdx.x == 0) s_cid = atomicAdd(&g_work, 1);
        __syncthreads();
        const int cid = s_cid;
        if (cid >= nchunks) break;
        const int row  = g_rows[cid >> 1];
        const int half = cid & 1;

        if (lane == 0) cnt[warp] = 0;
        __syncwarp();

        // this warp's 8KB: 512 uint4 starting at column (half*8192 + warp*2048)
        const int colq0 = half * 2048 + warp * 512;          // uint4 units
        const uint4* p = reinterpret_cast<const uint4*>(ppr)
                       + (size_t)row * (NN / 4) + colq0;

        uint4 A[16];
#pragma unroll
        for (int u = 0; u < 16; u++)
            A[u] = __ldcs(p + u * 32 + lane);

#pragma unroll
        for (int u = 0; u < 16; u++) {
            const uint4 q = A[u];
            if (q.x | q.y | q.z | q.w) {
                const int j0 = (colq0 + u * 32 + lane) * 4;  // column in [0,NN)
                if (q.x) { int t = atomicAdd(&cnt[warp], 1); if (t < 144) { jbuf[warp][t] = j0;     vbuf[warp][t] = __uint_as_float(q.x); } }
                if (q.y) { int t = atomicAdd(&cnt[warp], 1); if (t < 144) { jbuf[warp][t] = j0 + 1; vbuf[warp][t] = __uint_as_float(q.y); } }
                if (q.z) { int t = atomicAdd(&cnt[warp], 1); if (t < 144) { jbuf[warp][t] = j0 + 2; vbuf[warp][t] = __uint_as_float(q.z); } }
                if (q.w) { int t = atomicAdd(&cnt[warp], 1); if (t < 144) { jbuf[warp][t] = j0 + 3; vbuf[warp][t] = __uint_as_float(q.w); } }
            }
        }
        __syncwarp();

        float acc0 = 0.0f, acc1 = 0.0f;
        const int n = min(cnt[warp], 144);
#pragma unroll 2
        for (int k = 0; k < n; k++) {
            const float v = vbuf[warp][k];
            const float* er = g_enc + (size_t)jbuf[warp][k] * D_H;
            acc0 += v * __ldg(er + lane);
            acc1 += v * __ldg(er + lane + 32);
        }

        red[warp][lane]      = acc0;
        red[warp][lane + 32] = acc1;
        __syncthreads();
        if (threadIdx.x < D_H) {
            const int c = threadIdx.x;
            g_rowout2[half][(size_t)row * D_H + c] =
                red[0][c] + red[1][c] + red[2][c] + red[3][c];
        }
        __syncthreads();   // protect smem reuse on next iteration
    }
}

// ---------------------------------------------------------------------------
// K4 scatter: out[i,:] = rowout2[0][idx[i],:] + rowout2[1][idx[i],:]
// float4-vectorized; all traffic L2-resident.
// ---------------------------------------------------------------------------
__global__ void __launch_bounds__(256) scatter_kernel(float* __restrict__ out) {
    const int e4 = blockIdx.x * 256 + threadIdx.x;   // float4 elem in [0, BB*16)
    const int i  = e4 >> 4;
    const int c4 = e4 & 15;
    const long long o = (long long)g_idx[i] * 16 + c4;
    const float4 a = reinterpret_cast<const float4*>(g_rowout2[0])[o];
    const float4 b = reinterpret_cast<const float4*>(g_rowout2[1])[o];
    float4 r;
    r.x = a.x + b.x; r.y = a.y + b.y; r.z = a.z + b.z; r.w = a.w + b.w;
    reinterpret_cast<float4*>(out)[e4] = r;
}

// ---------------------------------------------------------------------------
extern "C" void kernel_launch(void* const* d_in, const int* in_sizes, int n_in,
                              void* d_out, int out_size) {
    const float* X   = (const float*)d_in[0];
    const float* ppr = (const float*)d_in[1];
    const float* W   = (const float*)d_in[2];
    const float* b   = (const float*)d_in[3];
    const int*   idx = (const int*)d_in[4];
    float* out = (float*)d_out;

    prep_kernel<<<32, 256>>>(idx);
    enc_kernel<<<NN / 32 + 4, 256>>>(X, W, b);
    gather_kernel<<<148 * 4, 128>>>(ppr);
    scatter_kernel<<<BB * D_H / 4 / 256, 256>>>(out);
}

// round 6
// speedup vs baseline: 1.1452x; 1.1452x over previous
#include <cuda_runtime.h>
#include <cstdint>

// Problem constants (fixed by reference)
#define NN    16384   // n_nodes
#define D_IN  128
#define D_H   64
#define BB    4096    // minibatch

// Device scratch (no allocations allowed)
__device__ float g_enc[NN * D_H];    // 4 MiB: encoder output
__device__ int   g_idx[BB];

// ---- cp.async helpers --------------------------------------------------
__device__ __forceinline__ void cpa16(uint32_t dst_smem, const void* src) {
    asm volatile("cp.async.cg.shared.global [%0], [%1], 16;\n"
                 :: "r"(dst_smem), "l"(src));
}
__device__ __forceinline__ void cpa_commit() {
    asm volatile("cp.async.commit_group;\n");
}
__device__ __forceinline__ void cpa_wait7() {
    asm volatile("cp.async.wait_group 7;\n");
}

// ---------------------------------------------------------------------------
// K1: enc = X @ W + b -> g_enc [NN,64].  16 extra blocks decode idx
// (int64 vs int32; detection window = odd words of entries 0..255, in-bounds
// for BOTH layouts; P(false|int32) = (1/16384)^256 ~ 0).
// ---------------------------------------------------------------------------
__global__ void __launch_bounds__(256) enc_kernel(const float* __restrict__ X,
                                                  const float* __restrict__ W,
                                                  const float* __restrict__ b,
                                                  const int* __restrict__ idx32) {
    if (blockIdx.x >= NN / 32) {
        const int tid = threadIdx.x;
        __shared__ int s_is64;
        if (tid == 0) s_is64 = 1;
        __syncthreads();
        if (idx32[2 * tid + 1] != 0) s_is64 = 0;   // safe window; benign race
        __syncthreads();
        const int i = (blockIdx.x - NN / 32) * 256 + tid;
        g_idx[i] = s_is64 ? idx32[2 * i] : idx32[i];
        return;
    }

    __shared__ float sW[D_IN * D_H];   // 32 KiB
    __shared__ float sX[32 * D_IN];    // 16 KiB
    const int tid = threadIdx.x;

    for (int i = tid; i < D_IN * D_H; i += 256) sW[i] = W[i];
    const int row0 = blockIdx.x * 32;
    for (int i = tid; i < 32 * D_IN; i += 256) sX[i] = X[(size_t)row0 * D_IN + i];
    __syncthreads();

    const int c  = tid & 63;
    const int r0 = tid >> 6;
    const float bc = b[c];
    float acc[8];
#pragma unroll
    for (int a = 0; a < 8; a++) acc[a] = bc;

#pragma unroll 4
    for (int k = 0; k < D_IN; k++) {
        const float w = sW[k * D_H + c];
#pragma unroll
        for (int a = 0; a < 8; a++)
            acc[a] += sX[(r0 + 4 * a) * D_IN + k] * w;
    }
#pragma unroll
    for (int a = 0; a < 8; a++)
        g_enc[(size_t)(row0 + r0 + 4 * a) * D_H + c] = acc[a];
}

// ---------------------------------------------------------------------------
// K2: out[i,:] = ppr[idx[i],:] @ enc.  One block (4 warps) per output row;
// each warp streams its 16KB quarter-row through an 8-stage x 512B cp.async
// smem ring (guaranteed 4KB in flight per warp, zero register cost), scans
// the lane's own 16B per stage (integer-OR zero test — valid: nonneg values,
// exact +0.0f zeros), appends nonzeros to a per-warp smem list, replays vs
// L2-resident g_enc, block-reduces, writes out directly.
// ---------------------------------------------------------------------------
__global__ void __launch_bounds__(128) gather_kernel(const float* __restrict__ ppr,
                                                     float* __restrict__ out) {
    __shared__ uint4 ring[4][8][32];   // [warp][stage][lane]  16 KiB
    __shared__ float vbuf[4][160];
    __shared__ int   jbuf[4][160];
    __shared__ int   cnt[4];
    __shared__ float red[4][D_H];

    const int i    = blockIdx.x;
    const int lane = threadIdx.x & 31;
    const int warp = threadIdx.x >> 5;

    if (lane == 0) cnt[warp] = 0;
    __syncwarp();

    const int row = g_idx[i];
    // this warp's quarter: 1024 uint4 starting at uint4-index warp*1024
    const uint4* src = reinterpret_cast<const uint4*>(ppr)
                     + (size_t)row * (NN / 4) + warp * 1024 + lane;
    const uint32_t rbase =
        (uint32_t)__cvta_generic_to_shared(&ring[warp][0][lane]);

    // prologue: fill 8 stages (one commit-group per stage)
#pragma unroll
    for (int s = 0; s < 8; s++) {
        cpa16(rbase + s * 512, src + s * 32);
        cpa_commit();
    }

    const int j0base = (warp * 1024 + lane) * 4;   // column of this lane's elem 0

#pragma unroll 8
    for (int it = 0; it < 32; it++) {
        cpa_wait7();                               // stage `it` has landed
        const uint4 q = ring[warp][it & 7][lane];  // sync read precedes async refill
        if (it + 8 < 32)
            cpa16(rbase + (it & 7) * 512, src + (it + 8) * 32);
        cpa_commit();                              // empty groups keep count aligned

        if (q.x | q.y | q.z | q.w) {
            const int j0 = j0base + it * 128;
            if (q.x) { int t = atomicAdd(&cnt[warp], 1); if (t < 160) { jbuf[warp][t] = j0;     vbuf[warp][t] = __uint_as_float(q.x); } }
            if (q.y) { int t = atomicAdd(&cnt[warp], 1); if (t < 160) { jbuf[warp][t] = j0 + 1; vbuf[warp][t] = __uint_as_float(q.y); } }
            if (q.z) { int t = atomicAdd(&cnt[warp], 1); if (t < 160) { jbuf[warp][t] = j0 + 2; vbuf[warp][t] = __uint_as_float(q.z); } }
            if (q.w) { int t = atomicAdd(&cnt[warp], 1); if (t < 160) { jbuf[warp][t] = j0 + 3; vbuf[warp][t] = __uint_as_float(q.w); } }
        }
    }
    __syncwarp();

    // replay nonzero list against L2-resident g_enc
    float acc0 = 0.0f, acc1 = 0.0f;
    const int n = min(cnt[warp], 160);
#pragma unroll 2
    for (int k = 0; k < n; k++) {
        const float v = vbuf[warp][k];
        const float* er = g_enc + (size_t)jbuf[warp][k] * D_H;
        acc0 += v * __ldg(er + lane);
        acc1 += v * __ldg(er + lane + 32);
    }

    red[warp][lane]      = acc0;
    red[warp][lane + 32] = acc1;
    __syncthreads();
    if (threadIdx.x < D_H) {
        const int c = threadIdx.x;
        out[(size_t)i * D_H + c] = red[0][c] + red[1][c] + red[2][c] + red[3][c];
    }
}

// ---------------------------------------------------------------------------
extern "C" void kernel_launch(void* const* d_in, const int* in_sizes, int n_in,
                              void* d_out, int out_size) {
    const float* X   = (const float*)d_in[0];
    const float* ppr = (const float*)d_in[1];
    const float* W   = (const float*)d_in[2];
    const float* b   = (const float*)d_in[3];
    const int*   idx = (const int*)d_in[4];
    float* out = (float*)d_out;

    enc_kernel<<<NN / 32 + 16, 256>>>(X, W, b, idx);
    gather_kernel<<<BB, 128>>>(ppr, out);
}

// round 7
// speedup vs baseline: 1.2333x; 1.0769x over previous
#include <cuda_runtime.h>
#include <cstdint>

// Problem constants (fixed by reference)
#define NN    16384   // n_nodes
#define D_IN  128
#define D_H   64
#define BB    4096    // minibatch

// Device scratch (no allocations allowed)
__device__ float g_enc[NN * D_H];    // 4 MiB: encoder output
__device__ int   g_idx[BB];

// ---------------------------------------------------------------------------
// K1: enc = X @ W + b -> g_enc [NN,64].  16 extra blocks decode idx
// (int64 vs int32; detection window = odd words of entries 0..255, in-bounds
// for BOTH layouts; P(false|int32) = (1/16384)^256 ~ 0).
// LDS-lean mainloop: per 4 k-iters, 8 broadcast LDS.128 (sX) + 4 LDS.32 (sW).
// ---------------------------------------------------------------------------
__global__ void __launch_bounds__(256) enc_kernel(const float* __restrict__ X,
                                                  const float* __restrict__ W,
                                                  const float* __restrict__ b,
                                                  const int* __restrict__ idx32) {
    if (blockIdx.x >= NN / 32) {
        const int tid = threadIdx.x;
        __shared__ int s_is64;
        if (tid == 0) s_is64 = 1;
        __syncthreads();
        if (idx32[2 * tid + 1] != 0) s_is64 = 0;   // safe window; benign race
        __syncthreads();
        const int i = (blockIdx.x - NN / 32) * 256 + tid;
        g_idx[i] = s_is64 ? idx32[2 * i] : idx32[i];
        return;
    }

    __shared__ float sW[D_IN * D_H];                 // 32 KiB
    __shared__ __align__(16) float sX[32 * D_IN];    // 16 KiB
    const int tid = threadIdx.x;

    for (int i = tid; i < D_IN * D_H; i += 256) sW[i] = W[i];
    const int row0 = blockIdx.x * 32;
    {   // vectorized X load: 32*128 floats = 1024 float4
        const float4* Xs = reinterpret_cast<const float4*>(X + (size_t)row0 * D_IN);
        float4* sX4 = reinterpret_cast<float4*>(sX);
#pragma unroll
        for (int u = 0; u < 4; u++) sX4[u * 256 + tid] = Xs[u * 256 + tid];
    }
    __syncthreads();

    const int c  = tid & 63;
    const int r0 = tid >> 6;
    const float bc = b[c];
    float acc[8];
#pragma unroll
    for (int a = 0; a < 8; a++) acc[a] = bc;

    const float4* sX4 = reinterpret_cast<const float4*>(sX);
#pragma unroll 2
    for (int k4 = 0; k4 < D_IN / 4; k4++) {
        float w0 = sW[(4 * k4 + 0) * D_H + c];
        float w1 = sW[(4 * k4 + 1) * D_H + c];
        float w2 = sW[(4 * k4 + 2) * D_H + c];
        float w3 = sW[(4 * k4 + 3) * D_H + c];
#pragma unroll
        for (int a = 0; a < 8; a++) {
            const float4 x = sX4[(r0 + 4 * a) * (D_IN / 4) + k4];  // broadcast
            acc[a] += x.x * w0 + x.y * w1 + x.z * w2 + x.w * w3;
        }
    }
#pragma unroll
    for (int a = 0; a < 8; a++)
        g_enc[(size_t)(row0 + r0 + 4 * a) * D_H + c] = acc[a];
}

// ---------------------------------------------------------------------------
// K2: out[i,:] = ppr[idx[i],:] @ enc  exploiting TOPK=128 sparsity.
// One block (4 warps) per output row; each warp scans its 16KB quarter-row.
// NEW: 4 prefetch.global.L2 up front request the ENTIRE quarter (lane covers
// one 128B line; no registers, no scoreboard) so the __ldcs stream hits L2
// instead of DRAM — effective MLP no longer capped by register liveness.
// Nonzeros (integer-OR test; values nonneg, zeros exact +0.0f) go to a
// per-warp smem list, replayed against L2-resident g_enc.
// ---------------------------------------------------------------------------
__global__ void __launch_bounds__(128) gather_kernel(const float* __restrict__ ppr,
                                                     float* __restrict__ out) {
    __shared__ float vbuf[4][160];
    __shared__ int   jbuf[4][160];
    __shared__ int   cnt[4];
    __shared__ float red[4][D_H];

    const int i    = blockIdx.x;
    const int lane = threadIdx.x & 31;
    const int warp = threadIdx.x >> 5;

    if (lane == 0) cnt[warp] = 0;
    __syncwarp();

    const int row = g_idx[i];
    const uint4* rowp = reinterpret_cast<const uint4*>(ppr) + (size_t)row * (NN / 4);
    const int base = warp * 1024;   // this warp's quarter: 1024 uint4 = 16KB

    // ---- request the whole quarter into L2 (4 instructions per lane) ----
    {
        const char* qb = reinterpret_cast<const char*>(rowp + base) + lane * 128;
#pragma unroll
        for (int g = 0; g < 4; g++)
            asm volatile("prefetch.global.L2 [%0];" :: "l"(qb + g * 4096));
    }

    float acc0 = 0.0f, acc1 = 0.0f;

    for (int it = 0; it < 32; it += 8) {
        uint4 buf[8];
#pragma unroll
        for (int u = 0; u < 8; u++)
            buf[u] = __ldcs(rowp + base + (it + u) * 32 + lane);

#pragma unroll
        for (int u = 0; u < 8; u++) {
            const uint4 q = buf[u];
            if (q.x | q.y | q.z | q.w) {
                const int j0 = (base + (it + u) * 32 + lane) * 4;
                if (q.x) { int t = atomicAdd(&cnt[warp], 1); if (t < 160) { jbuf[warp][t] = j0;     vbuf[warp][t] = __uint_as_float(q.x); } }
                if (q.y) { int t = atomicAdd(&cnt[warp], 1); if (t < 160) { jbuf[warp][t] = j0 + 1; vbuf[warp][t] = __uint_as_float(q.y); } }
                if (q.z) { int t = atomicAdd(&cnt[warp], 1); if (t < 160) { jbuf[warp][t] = j0 + 2; vbuf[warp][t] = __uint_as_float(q.z); } }
                if (q.w) { int t = atomicAdd(&cnt[warp], 1); if (t < 160) { jbuf[warp][t] = j0 + 3; vbuf[warp][t] = __uint_as_float(q.w); } }
            }
        }
    }
    __syncwarp();

    // ---- replay nonzero list ----
    const int n = min(cnt[warp], 160);
#pragma unroll 2
    for (int k = 0; k < n; k++) {
        const float v = vbuf[warp][k];
        const float* er = g_enc + (size_t)jbuf[warp][k] * D_H;
        acc0 += v * __ldg(er + lane);
        acc1 += v * __ldg(er + lane + 32);
    }

    red[warp][lane]      = acc0;
    red[warp][lane + 32] = acc1;
    __syncthreads();
    if (threadIdx.x < D_H) {
        const int c = threadIdx.x;
        out[(size_t)i * D_H + c] = red[0][c] + red[1][c] + red[2][c] + red[3][c];
    }
}

// ---------------------------------------------------------------------------
extern "C" void kernel_launch(void* const* d_in, const int* in_sizes, int n_in,
                              void* d_out, int out_size) {
    const float* X   = (const float*)d_in[0];
    const float* ppr = (const float*)d_in[1];
    const float* W   = (const float*)d_in[2];
    const float* b   = (const float*)d_in[3];
    const int*   idx = (const int*)d_in[4];
    float* out = (float*)d_out;

    enc_kernel<<<NN / 32 + 16, 256>>>(X, W, b, idx);
    gather_kernel<<<BB, 128>>>(ppr, out);
}

// round 8
// speedup vs baseline: 1.3740x; 1.1141x over previous
#include <cuda_runtime.h>
#include <cstdint>

// Problem constants (fixed by reference)
#define NN    16384   // n_nodes
#define D_IN  128
#define D_H   64
#define BB    4096    // minibatch

// Device scratch (no allocations allowed)
__device__ float g_enc[NN * D_H];    // 4 MiB: encoder output
__device__ int   g_idx[BB];

// ---------------------------------------------------------------------------
// K1: enc = X @ W + b -> g_enc [NN,64].  16 extra blocks decode idx
// (int64 vs int32; detection window = odd words of entries 0..255, in-bounds
// for BOTH layouts; P(false|int32) = (1/16384)^256 ~ 0).
// LDS-lean mainloop: per 4 k-iters, 8 broadcast LDS.128 (sX) + 4 LDS.32 (sW).
// ---------------------------------------------------------------------------
__global__ void __launch_bounds__(256) enc_kernel(const float* __restrict__ X,
                                                  const float* __restrict__ W,
                                                  const float* __restrict__ b,
                                                  const int* __restrict__ idx32) {
    if (blockIdx.x >= NN / 32) {
        const int tid = threadIdx.x;
        __shared__ int s_is64;
        if (tid == 0) s_is64 = 1;
        __syncthreads();
        if (idx32[2 * tid + 1] != 0) s_is64 = 0;   // safe window; benign race
        __syncthreads();
        const int i = (blockIdx.x - NN / 32) * 256 + tid;
        g_idx[i] = s_is64 ? idx32[2 * i] : idx32[i];
        return;
    }

    __shared__ float sW[D_IN * D_H];                 // 32 KiB
    __shared__ __align__(16) float sX[32 * D_IN];    // 16 KiB
    const int tid = threadIdx.x;

    for (int i = tid; i < D_IN * D_H; i += 256) sW[i] = W[i];
    const int row0 = blockIdx.x * 32;
    {   // vectorized X load: 32*128 floats = 1024 float4
        const float4* Xs = reinterpret_cast<const float4*>(X + (size_t)row0 * D_IN);
        float4* sX4 = reinterpret_cast<float4*>(sX);
#pragma unroll
        for (int u = 0; u < 4; u++) sX4[u * 256 + tid] = Xs[u * 256 + tid];
    }
    __syncthreads();

    const int c  = tid & 63;
    const int r0 = tid >> 6;
    const float bc = b[c];
    float acc[8];
#pragma unroll
    for (int a = 0; a < 8; a++) acc[a] = bc;

    const float4* sX4 = reinterpret_cast<const float4*>(sX);
#pragma unroll 2
    for (int k4 = 0; k4 < D_IN / 4; k4++) {
        float w0 = sW[(4 * k4 + 0) * D_H + c];
        float w1 = sW[(4 * k4 + 1) * D_H + c];
        float w2 = sW[(4 * k4 + 2) * D_H + c];
        float w3 = sW[(4 * k4 + 3) * D_H + c];
#pragma unroll
        for (int a = 0; a < 8; a++) {
            const float4 x = sX4[(r0 + 4 * a) * (D_IN / 4) + k4];  // broadcast
            acc[a] += x.x * w0 + x.y * w1 + x.z * w2 + x.w * w3;
        }
    }
#pragma unroll
    for (int a = 0; a < 8; a++)
        g_enc[(size_t)(row0 + r0 + 4 * a) * D_H + c] = acc[a];
}

// ---------------------------------------------------------------------------
// K2: out[i,:] = ppr[idx[i],:] @ enc  exploiting TOPK=128 sparsity.
// One block (4 warps) per output row; each warp streams its 16KB quarter-row
// as uint4 batches of 4 (16 buffer regs), integer-OR zero test (valid:
// nonneg values, exact +0.0f zeros), nonzeros to a per-warp smem list,
// replayed vs L2-resident g_enc. __launch_bounds__(128,14) pins regs <= ~36
// so 14 blocks (56 warps) are resident per SM: chip-wide outstanding-load
// pool grows ~1.6x vs the 48-reg/40-warp R2 build -> DRAM% up.
// ---------------------------------------------------------------------------
__global__ void __launch_bounds__(128, 14) gather_kernel(const float* __restrict__ ppr,
                                                         float* __restrict__ out) {
    __shared__ float vbuf[4][160];
    __shared__ int   jbuf[4][160];
    __shared__ int   cnt[4];
    __shared__ float red[4][D_H];

    const int i    = blockIdx.x;
    const int lane = threadIdx.x & 31;
    const int warp = threadIdx.x >> 5;

    if (lane == 0) cnt[warp] = 0;
    __syncwarp();

    const int row = g_idx[i];
    const uint4* rowp = reinterpret_cast<const uint4*>(ppr) + (size_t)row * (NN / 4);
    const int base = warp * 1024;   // this warp's quarter: 1024 uint4 = 16KB

    float acc0 = 0.0f, acc1 = 0.0f;

    for (int it = 0; it < 32; it += 4) {
        uint4 buf[4];
#pragma unroll
        for (int u = 0; u < 4; u++)
            buf[u] = __ldcs(rowp + base + (it + u) * 32 + lane);

#pragma unroll
        for (int u = 0; u < 4; u++) {
            const uint4 q = buf[u];
            if (q.x | q.y | q.z | q.w) {
                const int j0 = (base + (it + u) * 32 + lane) * 4;
                if (q.x) { int t = atomicAdd(&cnt[warp], 1); if (t < 160) { jbuf[warp][t] = j0;     vbuf[warp][t] = __uint_as_float(q.x); } }
                if (q.y) { int t = atomicAdd(&cnt[warp], 1); if (t < 160) { jbuf[warp][t] = j0 + 1; vbuf[warp][t] = __uint_as_float(q.y); } }
                if (q.z) { int t = atomicAdd(&cnt[warp], 1); if (t < 160) { jbuf[warp][t] = j0 + 2; vbuf[warp][t] = __uint_as_float(q.z); } }
                if (q.w) { int t = atomicAdd(&cnt[warp], 1); if (t < 160) { jbuf[warp][t] = j0 + 3; vbuf[warp][t] = __uint_as_float(q.w); } }
            }
        }
    }
    __syncwarp();

    // ---- replay nonzero list ----
    const int n = min(cnt[warp], 160);
#pragma unroll 2
    for (int k = 0; k < n; k++) {
        const float v = vbuf[warp][k];
        const float* er = g_enc + (size_t)jbuf[warp][k] * D_H;
        acc0 += v * __ldg(er + lane);
        acc1 += v * __ldg(er + lane + 32);
    }

    red[warp][lane]      = acc0;
    red[warp][lane + 32] = acc1;
    __syncthreads();
    if (threadIdx.x < D_H) {
        const int c = threadIdx.x;
        out[(size_t)i * D_H + c] = red[0][c] + red[1][c] + red[2][c] + red[3][c];
    }
}

// ---------------------------------------------------------------------------
extern "C" void kernel_launch(void* const* d_in, const int* in_sizes, int n_in,
                              void* d_out, int out_size) {
    const float* X   = (const float*)d_in[0];
    const float* ppr = (const float*)d_in[1];
    const float* W   = (const float*)d_in[2];
    const float* b   = (const float*)d_in[3];
    const int*   idx = (const int*)d_in[4];
    float* out = (float*)d_out;

    enc_kernel<<<NN / 32 + 16, 256>>>(X, W, b, idx);
    gather_kernel<<<BB, 128>>>(ppr, out);
}